// round 6
// baseline (speedup 1.0000x reference)
#include <cuda_runtime.h>
#include <math.h>

#define SEQ   1000
#define BATCH 256
#define NIN   700
#define H1    256
#define H2    256
#define NOUT  20
#define KPAD  704
#define W1COLS 956
#define W2COLS 512

// ---------------- device scratch (module-load allocated, no cudaMalloc) -----
__device__ float g_xw[SEQ * BATCH * H1];      // 256 MB: precomputed x_t @ W1x^T
__device__ float g_Bmat[KPAD * H1];           // W1x, i-major, zero-padded to 704
__device__ float g_WT1r[H1 * H1];             // W1 recurrent part, k-major [k][j]
__device__ float g_WT2[W2COLS * H2];          // W2, k-major [k][j]
__device__ float g_WoutT[H2 * NOUT];          // Wout, k-major [k][o]
__device__ float g_d1m[H1], g_r1[H1], g_d2m[H2], g_r2[H2], g_do[NOUT];

// Correctly-rounded float exp(-1/tau): IEEE f32 divide (matches XLA's f32
// divide), then double-precision exp rounded once to float. This bit-matches
// a correctly-rounded libm expf (glibc/ARM optimized-routines) for all
// practical inputs, unlike CUDA's 2-ulp device expf.
__device__ __forceinline__ float cr_exp_decay(float tau) {
    float a = -1.0f / tau;                // f32 RN divide
    return (float)exp((double)a);         // CR double exp -> single RN to f32
}

// ---------------- prep: transposes + decays --------------------------------
__global__ void prep_kernel(const float* __restrict__ W1,
                            const float* __restrict__ tm1,
                            const float* __restrict__ ta1,
                            const float* __restrict__ W2,
                            const float* __restrict__ tm2,
                            const float* __restrict__ ta2,
                            const float* __restrict__ Wout,
                            const float* __restrict__ tout) {
    int idx = blockIdx.x * blockDim.x + threadIdx.x;

    int r = idx;
    if (r < KPAD * H1) {                       // g_Bmat[i][j] = W1[j, i], pad 0
        int i = r / H1, j = r % H1;
        g_Bmat[r] = (i < NIN) ? W1[j * W1COLS + i] : 0.0f;
        return;
    }
    r -= KPAD * H1;
    if (r < H1 * H1) {                         // g_WT1r[k][j] = W1[j, 700+k]
        int k = r / H1, j = r % H1;
        g_WT1r[r] = W1[j * W1COLS + NIN + k];
        return;
    }
    r -= H1 * H1;
    if (r < W2COLS * H2) {                     // g_WT2[k][j] = W2[j, k]
        int k = r / H2, j = r % H2;
        g_WT2[r] = W2[j * W2COLS + k];
        return;
    }
    r -= W2COLS * H2;
    if (r < H2 * NOUT) {                       // g_WoutT[k][o] = Wout[o, k]
        int k = r / NOUT, o = r % NOUT;
        g_WoutT[r] = Wout[o * H2 + k];
        return;
    }
    r -= H2 * NOUT;
    if (r < H1)               { g_d1m[r] = cr_exp_decay(tm1[r]); return; }
    r -= H1;
    if (r < H1)               { g_r1[r]  = cr_exp_decay(ta1[r]); return; }
    r -= H1;
    if (r < H2)               { g_d2m[r] = cr_exp_decay(tm2[r]); return; }
    r -= H2;
    if (r < H2)               { g_r2[r]  = cr_exp_decay(ta2[r]); return; }
    r -= H2;
    if (r < NOUT)             { g_do[r]  = cr_exp_decay(tout[r]); return; }
}

// ---------------- xgemm: C[m, j] = sum_i X[m, i] * W1[j, i] ----------------
// M = SEQ*BATCH = 256000, N = 256, K = 700 (padded 704). fp32 SIMT, 128x128x8.
// Each output element is ONE sequential ascending-k FFMA chain (matches the
// per-element accumulation of a standard fp32 GEMM); the k=700..703 pads add
// exact +0.0 so the chain value equals the 700-term chain.
__global__ __launch_bounds__(256) void xgemm_kernel(const float* __restrict__ X) {
    __shared__ float As[8][128];
    __shared__ float Bs[8][128];

    const int m0 = blockIdx.x * 128;
    const int n0 = blockIdx.y * 128;
    const int tid = threadIdx.x;

    const int a_row = tid >> 1;            // 0..127
    const int a_col = (tid & 1) * 4;       // 0 or 4
    const int b_row = tid >> 5;            // 0..7
    const int b_col = (tid & 31) * 4;      // 0..124

    const int tm = (tid >> 4) * 8;         // 0..120
    const int tn = (tid & 15) * 8;         // 0..120

    const float* Xp = X + (size_t)(m0 + a_row) * NIN;

    float acc[8][8];
#pragma unroll
    for (int i = 0; i < 8; ++i)
#pragma unroll
        for (int j = 0; j < 8; ++j) acc[i][j] = 0.0f;

    for (int kt = 0; kt < KPAD; kt += 8) {
        // stage A (guard only at the 700-boundary tile)
        int k = kt + a_col;
        float4 av;
        if (k + 3 < NIN) {
            av = *(const float4*)(Xp + k);
        } else {
            av.x = (k + 0 < NIN) ? Xp[k + 0] : 0.0f;
            av.y = (k + 1 < NIN) ? Xp[k + 1] : 0.0f;
            av.z = (k + 2 < NIN) ? Xp[k + 2] : 0.0f;
            av.w = (k + 3 < NIN) ? Xp[k + 3] : 0.0f;
        }
        As[a_col + 0][a_row] = av.x;
        As[a_col + 1][a_row] = av.y;
        As[a_col + 2][a_row] = av.z;
        As[a_col + 3][a_row] = av.w;
        // stage B (already k-major, zero-padded)
        *(float4*)&Bs[b_row][b_col] =
            *(const float4*)&g_Bmat[(kt + b_row) * H1 + n0 + b_col];
        __syncthreads();

#pragma unroll
        for (int kk = 0; kk < 8; ++kk) {
            float a[8], b[8];
            *(float4*)&a[0] = *(const float4*)&As[kk][tm];
            *(float4*)&a[4] = *(const float4*)&As[kk][tm + 4];
            *(float4*)&b[0] = *(const float4*)&Bs[kk][tn];
            *(float4*)&b[4] = *(const float4*)&Bs[kk][tn + 4];
#pragma unroll
            for (int i = 0; i < 8; ++i)
#pragma unroll
                for (int j = 0; j < 8; ++j)
                    acc[i][j] = __fmaf_rn(a[i], b[j], acc[i][j]);
        }
        __syncthreads();
    }

#pragma unroll
    for (int i = 0; i < 8; ++i) {
        float* C = g_xw + (size_t)(m0 + tm + i) * H1 + n0 + tn;
        *(float4*)&C[0] = *(float4*)&acc[i][0];
        *(float4*)&C[4] = *(float4*)&acc[i][4];
    }
}

// ---------------- sequential ALIF recurrence: one CTA per batch sample -----
// All elementwise state math uses __fmul_rn/__fadd_rn/__fsub_rn (no FFMA
// contraction) to mirror XLA's non-contracted elementwise emission, and all
// dot products are single-accumulator ascending-k chains continuing the
// xgemm chain (z terms are exact +w adds since z == 1.0).
__global__ __launch_bounds__(256) void seq_kernel(float* __restrict__ out) {
    const int b    = blockIdx.x;
    const int j    = threadIdx.x;
    const int warp = j >> 5;
    const int lane = j & 31;
    const unsigned ltmask = (lane == 0) ? 0u : (0xffffffffu >> (32 - lane));

    __shared__ int L2[H1 + H2];   // [z1-actives | z2-actives+256], ascending
    __shared__ int Lo[H2];        // z2-actives (for output GEMV), ascending
    __shared__ int wc1[8], wc2[8], wco[8];

    const float d1 = g_d1m[j], rr1 = g_r1[j];
    const float d2 = g_d2m[j], rr2 = g_r2[j];
    const float om_d1 = __fsub_rn(1.0f, d1), om_r1 = __fsub_rn(1.0f, rr1);
    const float om_d2 = __fsub_rn(1.0f, d2), om_r2 = __fsub_rn(1.0f, rr2);

    float u1 = 0.0f, a1 = 0.0f, u2 = 0.0f, a2 = 0.0f;
    float z1 = 0.0f, z2 = 0.0f;
    float uo = 0.0f, dob = 0.0f, om_dob = 0.0f;
    if (j < NOUT) { dob = g_do[j]; om_dob = __fsub_rn(1.0f, dob); }

    int n1 = 0;
    const float* xwp = g_xw + (size_t)b * H1 + j;   // stride per step: BATCH*H1
    float xw = xwp[0];

    for (int t = 0; t < SEQ; ++t) {
        float xw_n = (t + 1 < SEQ) ? xwp[(size_t)(t + 1) * (BATCH * H1)] : 0.0f;

        // ---- layer 1: cur1 = chain(x-part) continued over z1 actives ----
        float cur1 = xw;
        {
            int i = 0;
            for (; i + 4 <= n1; i += 4) {
                float v0 = g_WT1r[(L2[i + 0] << 8) + j];
                float v1 = g_WT1r[(L2[i + 1] << 8) + j];
                float v2 = g_WT1r[(L2[i + 2] << 8) + j];
                float v3 = g_WT1r[(L2[i + 3] << 8) + j];
                cur1 = __fadd_rn(cur1, v0);
                cur1 = __fadd_rn(cur1, v1);
                cur1 = __fadd_rn(cur1, v2);
                cur1 = __fadd_rn(cur1, v3);
            }
            for (; i < n1; ++i)
                cur1 = __fadd_rn(cur1, g_WT1r[(L2[i] << 8) + j]);
        }

        // a = rho*a + (1-rho)*z ; theta = B0 + BETA*a
        a1 = __fadd_rn(__fmul_rn(rr1, a1), __fmul_rn(om_r1, z1));
        float th1 = __fadd_rn(0.01f, __fmul_rn(1.8f, a1));
        // u = alpha*u + (1-alpha)*cur - z*theta
        u1 = __fsub_rn(__fadd_rn(__fmul_rn(d1, u1), __fmul_rn(om_d1, cur1)),
                       __fmul_rn(z1, th1));
        float z1n = (__fsub_rn(u1, th1) > 0.0f) ? 1.0f : 0.0f;
        __syncthreads();                                        // S1
        z1 = z1n;

        // ---- build L2 = [act(z1_new) | act(z2_prev)+256], deterministic ----
        unsigned m1 = __ballot_sync(0xffffffffu, z1 != 0.0f);
        unsigned m2 = __ballot_sync(0xffffffffu, z2 != 0.0f);
        if (lane == 0) { wc1[warp] = __popc(m1); wc2[warp] = __popc(m2); }
        __syncthreads();                                        // S2
        int tot1 = 0, base1 = 0, tot2 = 0, base2 = 0;
#pragma unroll
        for (int w = 0; w < 8; ++w) {
            int c1 = wc1[w], c2 = wc2[w];
            if (w < warp) { base1 += c1; base2 += c2; }
            tot1 += c1; tot2 += c2;
        }
        base2 += tot1;
        if (z1 != 0.0f) L2[base1 + __popc(m1 & ltmask)] = j;
        if (z2 != 0.0f) L2[base2 + __popc(m2 & ltmask)] = H1 + j;
        n1 = tot1;
        const int n12 = tot1 + tot2;
        __syncthreads();                                        // S3

        // ---- layer 2: cur2 = chain over [z1_new actives, z2_prev actives] ----
        float cur2 = 0.0f;
        {
            int i = 0;
            for (; i + 4 <= n12; i += 4) {
                float v0 = g_WT2[(L2[i + 0] << 8) + j];
                float v1 = g_WT2[(L2[i + 1] << 8) + j];
                float v2 = g_WT2[(L2[i + 2] << 8) + j];
                float v3 = g_WT2[(L2[i + 3] << 8) + j];
                cur2 = __fadd_rn(cur2, v0);
                cur2 = __fadd_rn(cur2, v1);
                cur2 = __fadd_rn(cur2, v2);
                cur2 = __fadd_rn(cur2, v3);
            }
            for (; i < n12; ++i)
                cur2 = __fadd_rn(cur2, g_WT2[(L2[i] << 8) + j]);
        }

        a2 = __fadd_rn(__fmul_rn(rr2, a2), __fmul_rn(om_r2, z2));
        float th2 = __fadd_rn(0.01f, __fmul_rn(1.8f, a2));
        u2 = __fsub_rn(__fadd_rn(__fmul_rn(d2, u2), __fmul_rn(om_d2, cur2)),
                       __fmul_rn(z2, th2));
        float z2n = (__fsub_rn(u2, th2) > 0.0f) ? 1.0f : 0.0f;

        // ---- build Lo = act(z2_new) ----
        unsigned mo = __ballot_sync(0xffffffffu, z2n != 0.0f);
        if (lane == 0) wco[warp] = __popc(mo);
        __syncthreads();                                        // S4
        z2 = z2n;
        int baseo = 0, toto = 0;
#pragma unroll
        for (int w = 0; w < 8; ++w) {
            int c = wco[w];
            if (w < warp) baseo += c;
            toto += c;
        }
        if (z2 != 0.0f) Lo[baseo + __popc(mo & ltmask)] = j;
        const int no = toto;
        __syncthreads();                                        // S5

        // ---- output leaky integrator: uo = ao*uo + (1-ao)*(z2 @ Wout.T) ----
        if (j < NOUT) {
            float so = 0.0f;
            for (int q = 0; q < no; ++q)
                so = __fadd_rn(so, g_WoutT[Lo[q] * NOUT + j]);
            uo = __fadd_rn(__fmul_rn(dob, uo), __fmul_rn(om_dob, so));
            if (t > 0) out[((size_t)(t - 1) * BATCH + b) * NOUT + j] = uo;
        }
        xw = xw_n;
    }
}

// ---------------- launch ----------------------------------------------------
extern "C" void kernel_launch(void* const* d_in, const int* in_sizes, int n_in,
                              void* d_out, int out_size) {
    const float* x    = (const float*)d_in[0];
    const float* W1   = (const float*)d_in[1];
    const float* tm1  = (const float*)d_in[2];
    const float* ta1  = (const float*)d_in[3];
    const float* W2   = (const float*)d_in[4];
    const float* tm2  = (const float*)d_in[5];
    const float* ta2  = (const float*)d_in[6];
    const float* Wout = (const float*)d_in[7];
    const float* tout = (const float*)d_in[8];
    float* out = (float*)d_out;

    const int prep_total = KPAD * H1 + H1 * H1 + W2COLS * H2 + H2 * NOUT
                         + 2 * H1 + 2 * H2 + NOUT;
    prep_kernel<<<(prep_total + 255) / 256, 256>>>(W1, tm1, ta1, W2, tm2, ta2,
                                                   Wout, tout);

    dim3 gg((SEQ * BATCH) / 128, H1 / 128);   // (2000, 2)
    xgemm_kernel<<<gg, 256>>>(x);

    seq_kernel<<<BATCH, 256>>>(out);
}

// round 8
// speedup vs baseline: 1.0636x; 1.0636x over previous
#include <cuda_runtime.h>
#include <math.h>

#define SEQ   1000
#define BATCH 256
#define NIN   700
#define H1    256
#define H2    256
#define NOUT  20
#define KPAD  704
#define W1COLS 956
#define W2COLS 512

// ---------------- device scratch (module-load allocated, no cudaMalloc) -----
__device__ float g_xw[SEQ * BATCH * H1];      // 256 MB: precomputed x_t @ W1x^T
__device__ float g_Bmat[KPAD * H1];           // W1x, i-major, zero-padded to 704
__device__ float g_WT1r[H1 * H1];             // W1 recurrent part, k-major [k][j]
__device__ float g_WT2[W2COLS * H2];          // W2, k-major [k][j]
__device__ float g_WoutT[H2 * NOUT];          // Wout, k-major [k][o]
__device__ float g_d1m[H1], g_r1[H1], g_d2m[H2], g_r2[H2], g_do[NOUT];

// Correctly-rounded float exp(-1/tau): IEEE f32 divide, then double exp
// rounded once to float — bit-matches a correctly-rounded host expf.
__device__ __forceinline__ float cr_exp_decay(float tau) {
    float a = -1.0f / tau;
    return (float)exp((double)a);
}

// ---------------- prep: transposes + decays --------------------------------
__global__ void prep_kernel(const float* __restrict__ W1,
                            const float* __restrict__ tm1,
                            const float* __restrict__ ta1,
                            const float* __restrict__ W2,
                            const float* __restrict__ tm2,
                            const float* __restrict__ ta2,
                            const float* __restrict__ Wout,
                            const float* __restrict__ tout) {
    int idx = blockIdx.x * blockDim.x + threadIdx.x;

    int r = idx;
    if (r < KPAD * H1) {                       // g_Bmat[i][j] = W1[j, i], pad 0
        int i = r / H1, j = r % H1;
        g_Bmat[r] = (i < NIN) ? W1[j * W1COLS + i] : 0.0f;
        return;
    }
    r -= KPAD * H1;
    if (r < H1 * H1) {                         // g_WT1r[k][j] = W1[j, 700+k]
        int k = r / H1, j = r % H1;
        g_WT1r[r] = W1[j * W1COLS + NIN + k];
        return;
    }
    r -= H1 * H1;
    if (r < W2COLS * H2) {                     // g_WT2[k][j] = W2[j, k]
        int k = r / H2, j = r % H2;
        g_WT2[r] = W2[j * W2COLS + k];
        return;
    }
    r -= W2COLS * H2;
    if (r < H2 * NOUT) {                       // g_WoutT[k][o] = Wout[o, k]
        int k = r / NOUT, o = r % NOUT;
        g_WoutT[r] = Wout[o * H2 + k];
        return;
    }
    r -= H2 * NOUT;
    if (r < H1)               { g_d1m[r] = cr_exp_decay(tm1[r]); return; }
    r -= H1;
    if (r < H1)               { g_r1[r]  = cr_exp_decay(ta1[r]); return; }
    r -= H1;
    if (r < H2)               { g_d2m[r] = cr_exp_decay(tm2[r]); return; }
    r -= H2;
    if (r < H2)               { g_r2[r]  = cr_exp_decay(ta2[r]); return; }
    r -= H2;
    if (r < NOUT)             { g_do[r]  = cr_exp_decay(tout[r]); return; }
}

// ---------------- xgemm v2: C[m, j] = sum_i X[m, i] * W1[j, i] -------------
// M = 256000, N = 256, K = 704 (700 + exact-zero pad). 128x128x16 tiles,
// double-buffered smem, one barrier per k-tile. Each output element remains
// ONE sequential ascending-k FFMA chain -> bit-identical to the v1 result.
#define BK 16
#define NT (KPAD / BK)          // 44 tiles
#define ASTRIDE 132             // padded to kill STS bank conflicts

__global__ __launch_bounds__(256, 2) void xgemm_kernel(const float* __restrict__ X) {
    __shared__ float As[2][BK * ASTRIDE];   // [k][m], padded
    __shared__ float Bs[2][BK * 128];       // [k][n]

    const int m0 = blockIdx.x * 128;
    const int n0 = blockIdx.y * 128;
    const int tid = threadIdx.x;

    // A staging: 128 rows x 16 k = 512 float4; 2 per thread
    const int a_row  = tid >> 2;            // 0..63 (and +64)
    const int a_col  = (tid & 3) * 4;       // 0,4,8,12
    // B staging: 16 k-rows x 128 n = 512 float4; 2 per thread
    const int b_row  = tid >> 5;            // 0..7 (and +8)
    const int b_col  = (tid & 31) * 4;      // 0..124

    const int tm = (tid >> 4) * 8;          // 0..120
    const int tn = (tid & 15) * 8;          // 0..120

    const float* Xp0 = X + (size_t)(m0 + a_row) * NIN;
    const float* Xp1 = X + (size_t)(m0 + a_row + 64) * NIN;

    float acc[8][8];
#pragma unroll
    for (int i = 0; i < 8; ++i)
#pragma unroll
        for (int j = 0; j < 8; ++j) acc[i][j] = 0.0f;

    float4 ar0, ar1, br0, br1;

    // ---- load one tile's staging data into registers ----
    auto ldg_tile = [&](int kt) {
        int k = kt + a_col;
        if (k + 3 < NIN) {
            ar0 = *(const float4*)(Xp0 + k);
            ar1 = *(const float4*)(Xp1 + k);
        } else {
            ar0.x = (k + 0 < NIN) ? Xp0[k + 0] : 0.0f;
            ar0.y = (k + 1 < NIN) ? Xp0[k + 1] : 0.0f;
            ar0.z = (k + 2 < NIN) ? Xp0[k + 2] : 0.0f;
            ar0.w = (k + 3 < NIN) ? Xp0[k + 3] : 0.0f;
            ar1.x = (k + 0 < NIN) ? Xp1[k + 0] : 0.0f;
            ar1.y = (k + 1 < NIN) ? Xp1[k + 1] : 0.0f;
            ar1.z = (k + 2 < NIN) ? Xp1[k + 2] : 0.0f;
            ar1.w = (k + 3 < NIN) ? Xp1[k + 3] : 0.0f;
        }
        br0 = *(const float4*)&g_Bmat[(kt + b_row) * H1 + n0 + b_col];
        br1 = *(const float4*)&g_Bmat[(kt + b_row + 8) * H1 + n0 + b_col];
    };
    auto sts_tile = [&](int buf) {
        float* A = As[buf];
        A[(a_col + 0) * ASTRIDE + a_row] = ar0.x;
        A[(a_col + 1) * ASTRIDE + a_row] = ar0.y;
        A[(a_col + 2) * ASTRIDE + a_row] = ar0.z;
        A[(a_col + 3) * ASTRIDE + a_row] = ar0.w;
        A[(a_col + 0) * ASTRIDE + a_row + 64] = ar1.x;
        A[(a_col + 1) * ASTRIDE + a_row + 64] = ar1.y;
        A[(a_col + 2) * ASTRIDE + a_row + 64] = ar1.z;
        A[(a_col + 3) * ASTRIDE + a_row + 64] = ar1.w;
        float* B = Bs[buf];
        *(float4*)&B[b_row * 128 + b_col]       = br0;
        *(float4*)&B[(b_row + 8) * 128 + b_col] = br1;
    };

    ldg_tile(0);
    sts_tile(0);
    __syncthreads();

    int buf = 0;
    for (int ti = 0; ti < NT; ++ti) {
        const bool more = (ti + 1 < NT);
        if (more) ldg_tile((ti + 1) * BK);

        const float* A = As[buf];
        const float* B = Bs[buf];
#pragma unroll
        for (int kk = 0; kk < BK; ++kk) {
            float a[8], b[8];
            *(float4*)&a[0] = *(const float4*)&A[kk * ASTRIDE + tm];
            *(float4*)&a[4] = *(const float4*)&A[kk * ASTRIDE + tm + 4];
            *(float4*)&b[0] = *(const float4*)&B[kk * 128 + tn];
            *(float4*)&b[4] = *(const float4*)&B[kk * 128 + tn + 4];
#pragma unroll
            for (int i = 0; i < 8; ++i)
#pragma unroll
                for (int j = 0; j < 8; ++j)
                    acc[i][j] = __fmaf_rn(a[i], b[j], acc[i][j]);
        }

        if (more) {
            sts_tile(buf ^ 1);
            __syncthreads();
            buf ^= 1;
        }
    }

#pragma unroll
    for (int i = 0; i < 8; ++i) {
        float* C = g_xw + (size_t)(m0 + tm + i) * H1 + n0 + tn;
        *(float4*)&C[0] = *(float4*)&acc[i][0];
        *(float4*)&C[4] = *(float4*)&acc[i][4];
    }
}

// ---------------- sequential ALIF recurrence: one CTA per batch sample -----
// (unchanged from the passing round-6 kernel)
__global__ __launch_bounds__(256) void seq_kernel(float* __restrict__ out) {
    const int b    = blockIdx.x;
    const int j    = threadIdx.x;
    const int warp = j >> 5;
    const int lane = j & 31;
    const unsigned ltmask = (lane == 0) ? 0u : (0xffffffffu >> (32 - lane));

    __shared__ int L2[H1 + H2];   // [z1-actives | z2-actives+256], ascending
    __shared__ int Lo[H2];        // z2-actives (for output GEMV), ascending
    __shared__ int wc1[8], wc2[8], wco[8];

    const float d1 = g_d1m[j], rr1 = g_r1[j];
    const float d2 = g_d2m[j], rr2 = g_r2[j];
    const float om_d1 = __fsub_rn(1.0f, d1), om_r1 = __fsub_rn(1.0f, rr1);
    const float om_d2 = __fsub_rn(1.0f, d2), om_r2 = __fsub_rn(1.0f, rr2);

    float u1 = 0.0f, a1 = 0.0f, u2 = 0.0f, a2 = 0.0f;
    float z1 = 0.0f, z2 = 0.0f;
    float uo = 0.0f, dob = 0.0f, om_dob = 0.0f;
    if (j < NOUT) { dob = g_do[j]; om_dob = __fsub_rn(1.0f, dob); }

    int n1 = 0;
    const float* xwp = g_xw + (size_t)b * H1 + j;   // stride per step: BATCH*H1
    float xw = xwp[0];

    for (int t = 0; t < SEQ; ++t) {
        float xw_n = (t + 1 < SEQ) ? xwp[(size_t)(t + 1) * (BATCH * H1)] : 0.0f;

        // ---- layer 1: cur1 = chain(x-part) continued over z1 actives ----
        float cur1 = xw;
        {
            int i = 0;
            for (; i + 4 <= n1; i += 4) {
                float v0 = g_WT1r[(L2[i + 0] << 8) + j];
                float v1 = g_WT1r[(L2[i + 1] << 8) + j];
                float v2 = g_WT1r[(L2[i + 2] << 8) + j];
                float v3 = g_WT1r[(L2[i + 3] << 8) + j];
                cur1 = __fadd_rn(cur1, v0);
                cur1 = __fadd_rn(cur1, v1);
                cur1 = __fadd_rn(cur1, v2);
                cur1 = __fadd_rn(cur1, v3);
            }
            for (; i < n1; ++i)
                cur1 = __fadd_rn(cur1, g_WT1r[(L2[i] << 8) + j]);
        }

        a1 = __fadd_rn(__fmul_rn(rr1, a1), __fmul_rn(om_r1, z1));
        float th1 = __fadd_rn(0.01f, __fmul_rn(1.8f, a1));
        u1 = __fsub_rn(__fadd_rn(__fmul_rn(d1, u1), __fmul_rn(om_d1, cur1)),
                       __fmul_rn(z1, th1));
        float z1n = (__fsub_rn(u1, th1) > 0.0f) ? 1.0f : 0.0f;
        __syncthreads();                                        // S1
        z1 = z1n;

        // ---- build L2 = [act(z1_new) | act(z2_prev)+256], deterministic ----
        unsigned m1 = __ballot_sync(0xffffffffu, z1 != 0.0f);
        unsigned m2 = __ballot_sync(0xffffffffu, z2 != 0.0f);
        if (lane == 0) { wc1[warp] = __popc(m1); wc2[warp] = __popc(m2); }
        __syncthreads();                                        // S2
        int tot1 = 0, base1 = 0, tot2 = 0, base2 = 0;
#pragma unroll
        for (int w = 0; w < 8; ++w) {
            int c1 = wc1[w], c2 = wc2[w];
            if (w < warp) { base1 += c1; base2 += c2; }
            tot1 += c1; tot2 += c2;
        }
        base2 += tot1;
        if (z1 != 0.0f) L2[base1 + __popc(m1 & ltmask)] = j;
        if (z2 != 0.0f) L2[base2 + __popc(m2 & ltmask)] = H1 + j;
        n1 = tot1;
        const int n12 = tot1 + tot2;
        __syncthreads();                                        // S3

        // ---- layer 2: cur2 = chain over [z1_new actives, z2_prev actives] ----
        float cur2 = 0.0f;
        {
            int i = 0;
            for (; i + 4 <= n12; i += 4) {
                float v0 = g_WT2[(L2[i + 0] << 8) + j];
                float v1 = g_WT2[(L2[i + 1] << 8) + j];
                float v2 = g_WT2[(L2[i + 2] << 8) + j];
                float v3 = g_WT2[(L2[i + 3] << 8) + j];
                cur2 = __fadd_rn(cur2, v0);
                cur2 = __fadd_rn(cur2, v1);
                cur2 = __fadd_rn(cur2, v2);
                cur2 = __fadd_rn(cur2, v3);
            }
            for (; i < n12; ++i)
                cur2 = __fadd_rn(cur2, g_WT2[(L2[i] << 8) + j]);
        }

        a2 = __fadd_rn(__fmul_rn(rr2, a2), __fmul_rn(om_r2, z2));
        float th2 = __fadd_rn(0.01f, __fmul_rn(1.8f, a2));
        u2 = __fsub_rn(__fadd_rn(__fmul_rn(d2, u2), __fmul_rn(om_d2, cur2)),
                       __fmul_rn(z2, th2));
        float z2n = (__fsub_rn(u2, th2) > 0.0f) ? 1.0f : 0.0f;

        // ---- build Lo = act(z2_new) ----
        unsigned mo = __ballot_sync(0xffffffffu, z2n != 0.0f);
        if (lane == 0) wco[warp] = __popc(mo);
        __syncthreads();                                        // S4
        z2 = z2n;
        int baseo = 0, toto = 0;
#pragma unroll
        for (int w = 0; w < 8; ++w) {
            int c = wco[w];
            if (w < warp) baseo += c;
            toto += c;
        }
        if (z2 != 0.0f) Lo[baseo + __popc(mo & ltmask)] = j;
        const int no = toto;
        __syncthreads();                                        // S5

        // ---- output leaky integrator: uo = ao*uo + (1-ao)*(z2 @ Wout.T) ----
        if (j < NOUT) {
            float so = 0.0f;
            for (int q = 0; q < no; ++q)
                so = __fadd_rn(so, g_WoutT[Lo[q] * NOUT + j]);
            uo = __fadd_rn(__fmul_rn(dob, uo), __fmul_rn(om_dob, so));
            if (t > 0) out[((size_t)(t - 1) * BATCH + b) * NOUT + j] = uo;
        }
        xw = xw_n;
    }
}

// ---------------- launch ----------------------------------------------------
extern "C" void kernel_launch(void* const* d_in, const int* in_sizes, int n_in,
                              void* d_out, int out_size) {
    const float* x    = (const float*)d_in[0];
    const float* W1   = (const float*)d_in[1];
    const float* tm1  = (const float*)d_in[2];
    const float* ta1  = (const float*)d_in[3];
    const float* W2   = (const float*)d_in[4];
    const float* tm2  = (const float*)d_in[5];
    const float* ta2  = (const float*)d_in[6];
    const float* Wout = (const float*)d_in[7];
    const float* tout = (const float*)d_in[8];
    float* out = (float*)d_out;

    const int prep_total = KPAD * H1 + H1 * H1 + W2COLS * H2 + H2 * NOUT
                         + 2 * H1 + 2 * H2 + NOUT;
    prep_kernel<<<(prep_total + 255) / 256, 256>>>(W1, tm1, ta1, W2, tm2, ta2,
                                                   Wout, tout);

    dim3 gg((SEQ * BATCH) / 128, H1 / 128);   // (2000, 2)
    xgemm_kernel<<<gg, 256>>>(x);

    seq_kernel<<<BATCH, 256>>>(out);
}